// round 7
// baseline (speedup 1.0000x reference)
#include <cuda_runtime.h>
#include <cstdint>

#define THREADS 256
#define ROW_LEN 16384
#define KSEL 64
#define SEGW 13                        // per-thread segment stride (words), coprime with 32
#define NSLOT 12                       // usable candidate slots per thread
#define CAND_WORDS (THREADS * SEGW + 64)  // + tail pad for overflow spray
#define T0F 2.30f                      // filter; exact fallback covers any input

// Monotonic transform (winners + fallback path only).
__device__ __forceinline__ uint32_t fwd_xform(uint32_t u) {
    return (u & 0x80000000u) ? ~u : (u | 0x80000000u);
}
__device__ __forceinline__ float inv_xform(uint32_t u) {
    return __uint_as_float((u & 0x80000000u) ? (u ^ 0x80000000u) : ~u);
}

// Warp-aggregated histogram add (small candidate set only).
__device__ __forceinline__ void hist_add(uint32_t* hist, uint32_t digit,
                                         bool active, int lane) {
    uint32_t key = active ? digit : (0x1000u | (uint32_t)lane);
    unsigned m = __match_any_sync(0xFFFFFFFFu, key);
    if (active && lane == (__ffs(m) - 1))
        atomicAdd(&hist[digit], (uint32_t)__popc(m));
}

// Branchless, atomic-free push: unconditional clamped store, conditional
// cursor advance. Junk stores are overwritten or land at [cnt] with a value
// <= T0F, which can never reach top-64 (fallback guarantees >=64 above T0F).
__device__ __forceinline__ void push(float f, uint32_t*& p) {
    *p = __float_as_uint(fmaxf(f, 0.0f));
    p += (f > T0F);
}

__global__ void __launch_bounds__(THREADS, 4)
topk64_kernel(const float* __restrict__ x, float* __restrict__ out) {
    __shared__ uint32_t cand[CAND_WORDS];   // raw non-negative float bits
    __shared__ uint32_t hist[256];
    __shared__ uint32_t sel[KSEL];          // transformed domain
    __shared__ uint32_t wsum[THREADS / 32];
    __shared__ uint32_t misc[4];  // [0]=fb flag, [1]=radix prefix, [2]=krem, [3]=sel cnt

    const int row  = blockIdx.x;
    const int tid  = threadIdx.x;
    const int lane = tid & 31;
    const int wid  = tid >> 5;

    const uint32_t* src  = reinterpret_cast<const uint32_t*>(x) + (size_t)row * ROW_LEN;
    const float4*   src4 = reinterpret_cast<const float4*>(src);

    // Zero-fill candidate buffer (filler 0 = smallest).
    #pragma unroll
    for (int i = tid; i < CAND_WORDS; i += THREADS) cand[i] = 0;
    __syncthreads();

    uint32_t* seg = cand + tid * SEGW;
    uint32_t* p   = seg;

    // ---- Phase 1: single global pass, front-batched loads, branchless filter ----
    #pragma unroll
    for (int ot = 0; ot < 2; ++ot) {
        float4 v[8];
        #pragma unroll
        for (int j = 0; j < 8; ++j)
            v[j] = src4[(ot * 8 + j) * THREADS + tid];
        #pragma unroll
        for (int j = 0; j < 8; ++j) {
            push(v[j].x, p);
            push(v[j].y, p);
            push(v[j].z, p);
            push(v[j].w, p);
        }
    }

    // ---- Fallback check: any per-thread overflow, or fewer than 64 total ----
    const uint32_t cnt = (uint32_t)(p - seg);
    hist[tid] = 0;
    if (tid == 0) { misc[1] = 0; misc[2] = KSEL; misc[3] = 0; }
    const uint32_t wtot = __reduce_add_sync(0xFFFFFFFFu, cnt);
    if (lane == 0) wsum[wid] = wtot;
    const int novf = __syncthreads_count((int)(cnt > NSLOT));  // barrier covers all above
    if (tid == 0) {
        uint32_t total = 0;
        #pragma unroll
        for (int w = 0; w < THREADS / 32; ++w) total += wsum[w];
        misc[0] = (novf > 0) || (total < KSEL);
    }
    __syncthreads();
    const bool fb = (misc[0] != 0);

    uint32_t T;  // transformed-domain bit pattern of the 64th largest

    if (!fb) {
        // ---- Phase 2: exact radix-select over raw bits (all non-negative) ----
        #pragma unroll
        for (int i = 0; i < SEGW; ++i)
            hist_add(hist, seg[i] >> 24, true, lane);
        __syncthreads();

        #pragma unroll 1
        for (int pass = 0; pass < 4; ++pass) {
            const int shift = 24 - 8 * pass;
            if (tid < 32) {  // warp 0: suffix-scan digit find over 256 bins
                uint32_t h[8]; uint32_t t = 0;
                #pragma unroll
                for (int j = 0; j < 8; ++j) { h[j] = hist[tid * 8 + j]; t += h[j]; }
                uint32_t s = t;
                #pragma unroll
                for (int off = 1; off < 32; off <<= 1) {
                    uint32_t vv = __shfl_down_sync(0xFFFFFFFFu, s, off);
                    if (tid + off < 32) s += vv;
                }
                const uint32_t krem = misc[2];
                uint32_t c = s - t;
                #pragma unroll
                for (int j = 7; j >= 0; --j) {
                    uint32_t nc = c + h[j];
                    if (nc >= krem && c < krem) {
                        misc[1] |= (uint32_t)(tid * 8 + j) << shift;
                        misc[2] = krem - c;
                    }
                    c = nc;
                }
            }
            __syncthreads();
            if (pass == 3) break;

            hist[tid] = 0;
            const uint32_t prefix = misc[1];
            __syncthreads();

            const int nshift = shift - 8;
            const uint32_t mask = ~((1u << shift) - 1u);
            #pragma unroll
            for (int i = 0; i < SEGW; ++i) {
                uint32_t u = seg[i];
                hist_add(hist, (u >> nshift) & 255u, (u & mask) == prefix, lane);
            }
            __syncthreads();
        }
        const uint32_t Traw = misc[1];
        T = Traw | 0x80000000u;  // non-negative raw -> transformed

        // Compact strict survivors (> Traw); exactly KSEL - krem <= 63 of them.
        #pragma unroll
        for (int i = 0; i < SEGW; ++i) {
            uint32_t u = seg[i];
            if (u > Traw) {
                uint32_t pos = atomicAdd(&misc[3], 1u);
                if (pos < KSEL) sel[pos] = u | 0x80000000u;
            }
        }
    } else {
        // ---- Fallback (exact, any input): bitwise search over the full row ----
        T = 0;
        #pragma unroll 1
        for (int b = 31; b >= 0; --b) {
            uint32_t c = T | (1u << b);
            int loc = 0;
            for (int i = tid; i < ROW_LEN; i += THREADS)
                loc += (int)(fwd_xform(src[i]) >= c);
            int wsumc = __reduce_add_sync(0xFFFFFFFFu, loc);
            if (tid == 0) misc[3] = 0;
            __syncthreads();
            if (lane == 0) atomicAdd(&misc[3], (uint32_t)wsumc);
            __syncthreads();
            if (misc[3] >= KSEL) T = c;
            __syncthreads();
        }
        if (tid == 0) misc[3] = 0;
        __syncthreads();
        for (int i = tid; i < ROW_LEN; i += THREADS) {
            uint32_t u = fwd_xform(src[i]);
            if (u > T) {
                uint32_t pos = atomicAdd(&misc[3], 1u);
                if (pos < KSEL) sel[pos] = u;
            }
        }
    }

    __syncthreads();
    const uint32_t cgt = misc[3];
    if (tid >= (int)cgt && tid < KSEL) sel[tid] = T;  // tie fill
    __syncthreads();

    // ---- Phase 3: rank-sort the 64 winners (descending), write ----
    if (tid < KSEL) {
        uint32_t v = sel[tid];
        int rank = 0;
        #pragma unroll
        for (int j = 0; j < KSEL; ++j) {
            uint32_t u = sel[j];
            rank += (int)((u > v) | ((u == v) & (j < tid)));
        }
        out[(size_t)row * KSEL + rank] = inv_xform(v);
    }
}

extern "C" void kernel_launch(void* const* d_in, const int* in_sizes, int n_in,
                              void* d_out, int out_size) {
    const float* x = (const float*)d_in[0];
    float* out = (float*)d_out;
    int rows = in_sizes[0] / ROW_LEN;  // 8192
    topk64_kernel<<<rows, THREADS>>>(x, out);
}

// round 8
// speedup vs baseline: 2.6069x; 2.6069x over previous
#include <cuda_runtime.h>
#include <cstdint>

#define ROW_LEN   16384
#define KSEL      64
#define MAXROWS   8192
#define UNITS_PER_ROW 16          // 2 CTAs/row x 8 warps
#define SEG       48              // candidate slots per warp-unit
#define CAP       (UNITS_PER_ROW * SEG)   // 768 words scanned by K2
#define T0F       2.30f           // filter threshold; exact fallback covers any input

// Global scratch (static — no allocations).
__device__ uint32_t g_cnt[MAXROWS * UNITS_PER_ROW];
__device__ uint32_t g_seg[MAXROWS * UNITS_PER_ROW * SEG];   // ~25 MB

// Monotonic transform: descending float order == descending uint order.
__device__ __forceinline__ uint32_t fwd_xform(uint32_t u) {
    return (u & 0x80000000u) ? ~u : (u | 0x80000000u);
}
__device__ __forceinline__ float inv_xform(uint32_t u) {
    return __uint_as_float((u & 0x80000000u) ? (u ^ 0x80000000u) : ~u);
}

// Warp-aggregated histogram add (small candidate set only).
__device__ __forceinline__ void hist_add(uint32_t* hist, uint32_t digit,
                                         bool active, int lane) {
    uint32_t key = active ? digit : (0x1000u | (uint32_t)lane);
    unsigned m = __match_any_sync(0xFFFFFFFFu, key);
    if (active && lane == (__ffs(m) - 1))
        atomicAdd(&hist[digit], (uint32_t)__popc(m));
}

// ---------------------------------------------------------------------------
// K1: pure streaming filter. One CTA per half-row (8192 elems, 32/thread).
// Round-4-proven push pattern; tiny smem so 6 CTAs/SM are resident.
// ---------------------------------------------------------------------------
__global__ void __launch_bounds__(256, 6)
filter_kernel(const float* __restrict__ x) {
    __shared__ uint32_t wcnt[8];
    __shared__ uint32_t stage[8 * SEG];

    const int cta  = blockIdx.x;
    const int tid  = threadIdx.x;
    const int wid  = tid >> 5;

    if (tid < 8) wcnt[tid] = 0;
    __syncthreads();

    const float4* src4 = reinterpret_cast<const float4*>(x) + (size_t)cta * 2048;

    #pragma unroll
    for (int ot = 0; ot < 2; ++ot) {
        float4 v[4];
        #pragma unroll
        for (int j = 0; j < 4; ++j)
            v[j] = src4[(ot * 4 + j) * 256 + tid];
        #pragma unroll
        for (int j = 0; j < 4; ++j) {
            float f[4] = {v[j].x, v[j].y, v[j].z, v[j].w};
            #pragma unroll
            for (int c = 0; c < 4; ++c) {
                if (f[c] > T0F) {
                    uint32_t pos = atomicAdd(&wcnt[wid], 1u);
                    if (pos < SEG) stage[wid * SEG + pos] = __float_as_uint(f[c]);
                }
            }
        }
    }
    __syncthreads();

    const uint32_t unitbase = (uint32_t)cta * 8;
    if (tid < 8) g_cnt[unitbase + tid] = wcnt[tid];
    // Copy only valid slots (~11/warp expected) to global segments.
    for (int i = tid; i < 8 * SEG; i += 256) {
        int w = i / SEG, s = i - w * SEG;
        uint32_t c = wcnt[w];
        if ((uint32_t)s < (c < SEG ? c : (uint32_t)SEG))
            g_seg[(unitbase + w) * SEG + s] = stage[i];
    }
}

// ---------------------------------------------------------------------------
// K2: exact top-64 select per row from gathered candidates (or full-row
// fallback). One CTA per row.
// ---------------------------------------------------------------------------
__global__ void __launch_bounds__(256)
select_kernel(const float* __restrict__ x, float* __restrict__ out) {
    __shared__ uint32_t cand[CAP];     // transformed domain (candidates | 0 filler)
    __shared__ uint32_t hist[256];
    __shared__ uint32_t sel[KSEL];     // transformed domain
    __shared__ uint32_t scnt[UNITS_PER_ROW];
    __shared__ uint32_t misc[4];       // [0]=fb, [1]=prefix, [2]=krem, [3]=sel cnt

    const int row  = blockIdx.x;
    const int tid  = threadIdx.x;
    const int lane = tid & 31;

    if (tid < UNITS_PER_ROW) scnt[tid] = g_cnt[row * UNITS_PER_ROW + tid];
    hist[tid] = 0;
    if (tid == 0) { misc[1] = 0; misc[2] = KSEL; misc[3] = 0; }
    __syncthreads();

    // Gather candidates into smem (transformed: raw positive | MSB).
    #pragma unroll
    for (int it = 0; it < CAP / 256; ++it) {
        int idx = it * 256 + tid;
        int u = idx / SEG, s = idx - u * SEG;
        uint32_t c = scnt[u];
        uint32_t v = ((uint32_t)s < c && c <= SEG)
                   ? g_seg[(row * UNITS_PER_ROW + u) * SEG + s] : 0u;
        cand[idx] = v ? (v | 0x80000000u) : 0u;
    }
    if (tid == 0) {
        uint32_t total = 0, ovf = 0;
        #pragma unroll
        for (int u = 0; u < UNITS_PER_ROW; ++u) {
            total += scnt[u];
            ovf |= (scnt[u] > SEG);
        }
        misc[0] = ovf || (total < KSEL);
    }
    __syncthreads();
    const bool fb = (misc[0] != 0);

    uint32_t T;  // transformed bit pattern of the 64th largest

    if (!fb) {
        // MSB-byte histogram over the 768-word buffer (zeros land in bin 0,
        // harmless: >=64 real candidates dominate the suffix).
        #pragma unroll
        for (int it = 0; it < CAP / 256; ++it)
            hist_add(hist, cand[it * 256 + tid] >> 24, true, lane);
        __syncthreads();

        #pragma unroll 1
        for (int pass = 0; pass < 4; ++pass) {
            const int shift = 24 - 8 * pass;
            if (tid < 32) {  // warp 0: suffix-scan digit find over 256 bins
                uint32_t h[8]; uint32_t t = 0;
                #pragma unroll
                for (int j = 0; j < 8; ++j) { h[j] = hist[tid * 8 + j]; t += h[j]; }
                uint32_t s = t;
                #pragma unroll
                for (int off = 1; off < 32; off <<= 1) {
                    uint32_t vv = __shfl_down_sync(0xFFFFFFFFu, s, off);
                    if (tid + off < 32) s += vv;
                }
                const uint32_t krem = misc[2];
                uint32_t c = s - t;
                #pragma unroll
                for (int j = 7; j >= 0; --j) {
                    uint32_t nc = c + h[j];
                    if (nc >= krem && c < krem) {
                        misc[1] |= (uint32_t)(tid * 8 + j) << shift;
                        misc[2] = krem - c;
                    }
                    c = nc;
                }
            }
            __syncthreads();
            if (pass == 3) break;

            hist[tid] = 0;
            const uint32_t prefix = misc[1];
            __syncthreads();

            const int nshift = shift - 8;
            const uint32_t mask = ~((1u << shift) - 1u);
            #pragma unroll
            for (int it = 0; it < CAP / 256; ++it) {
                uint32_t u = cand[it * 256 + tid];
                hist_add(hist, (u >> nshift) & 255u, (u & mask) == prefix, lane);
            }
            __syncthreads();
        }
        T = misc[1];

        // Compact strict survivors (> T); exactly KSEL - krem <= 63.
        #pragma unroll
        for (int it = 0; it < CAP / 256; ++it) {
            uint32_t u = cand[it * 256 + tid];
            if (u > T) {
                uint32_t pos = atomicAdd(&misc[3], 1u);
                if (pos < KSEL) sel[pos] = u;
            }
        }
    } else {
        // Exact fallback over the full row (handles any input distribution).
        const uint32_t* src = reinterpret_cast<const uint32_t*>(x) + (size_t)row * ROW_LEN;
        T = 0;
        #pragma unroll 1
        for (int b = 31; b >= 0; --b) {
            uint32_t c = T | (1u << b);
            int loc = 0;
            for (int i = tid; i < ROW_LEN; i += 256)
                loc += (int)(fwd_xform(src[i]) >= c);
            int wsumc = __reduce_add_sync(0xFFFFFFFFu, loc);
            if (tid == 0) misc[3] = 0;
            __syncthreads();
            if (lane == 0) atomicAdd(&misc[3], (uint32_t)wsumc);
            __syncthreads();
            if (misc[3] >= KSEL) T = c;
            __syncthreads();
        }
        if (tid == 0) misc[3] = 0;
        __syncthreads();
        for (int i = tid; i < ROW_LEN; i += 256) {
            uint32_t u = fwd_xform(src[i]);
            if (u > T) {
                uint32_t pos = atomicAdd(&misc[3], 1u);
                if (pos < KSEL) sel[pos] = u;
            }
        }
    }

    __syncthreads();
    const uint32_t cgt = misc[3];
    if (tid >= (int)cgt && tid < KSEL) sel[tid] = T;  // tie fill
    __syncthreads();

    // Rank-sort the 64 winners (descending) and write.
    if (tid < KSEL) {
        uint32_t v = sel[tid];
        int rank = 0;
        #pragma unroll
        for (int j = 0; j < KSEL; ++j) {
            uint32_t u = sel[j];
            rank += (int)((u > v) | ((u == v) & (j < tid)));
        }
        out[(size_t)row * KSEL + rank] = inv_xform(v);
    }
}

extern "C" void kernel_launch(void* const* d_in, const int* in_sizes, int n_in,
                              void* d_out, int out_size) {
    const float* x = (const float*)d_in[0];
    float* out = (float*)d_out;
    int rows = in_sizes[0] / ROW_LEN;
    if (rows > MAXROWS) rows = MAXROWS;
    filter_kernel<<<rows * 2, 256>>>(x);
    select_kernel<<<rows, 256>>>(x, out);
}

// round 9
// speedup vs baseline: 4.8935x; 1.8771x over previous
#include <cuda_runtime.h>
#include <cstdint>

#define ROW_LEN   16384
#define KSEL      64
#define MAXROWS   8192
#define UNITS_PER_ROW 16          // 2 CTAs/row x 8 warps in K1
#define SEG       48              // candidate slots per warp-unit
#define T0F       2.30f           // filter threshold; exact fallback covers any input
#define K2_WARPS  8

// Global scratch (static — no allocations).
__device__ uint32_t g_cnt[MAXROWS * UNITS_PER_ROW];
__device__ uint32_t g_seg[MAXROWS * UNITS_PER_ROW * SEG];   // ~25 MB (L2-resident)

// Monotonic transform: descending float order == descending uint order.
__device__ __forceinline__ uint32_t fwd_xform(uint32_t u) {
    return (u & 0x80000000u) ? ~u : (u | 0x80000000u);
}
__device__ __forceinline__ float inv_xform(uint32_t u) {
    return __uint_as_float((u & 0x80000000u) ? (u ^ 0x80000000u) : ~u);
}

// ---------------------------------------------------------------------------
// K1: pure streaming filter. One CTA per half-row (8192 elems, 32/thread).
// Proven at ~81 us (~6.3 TB/s). Unchanged.
// ---------------------------------------------------------------------------
__global__ void __launch_bounds__(256, 6)
filter_kernel(const float* __restrict__ x) {
    __shared__ uint32_t wcnt[8];
    __shared__ uint32_t stage[8 * SEG];

    const int cta  = blockIdx.x;
    const int tid  = threadIdx.x;
    const int wid  = tid >> 5;

    if (tid < 8) wcnt[tid] = 0;
    __syncthreads();

    const float4* src4 = reinterpret_cast<const float4*>(x) + (size_t)cta * 2048;

    #pragma unroll
    for (int ot = 0; ot < 2; ++ot) {
        float4 v[4];
        #pragma unroll
        for (int j = 0; j < 4; ++j)
            v[j] = src4[(ot * 4 + j) * 256 + tid];
        #pragma unroll
        for (int j = 0; j < 4; ++j) {
            float f[4] = {v[j].x, v[j].y, v[j].z, v[j].w};
            #pragma unroll
            for (int c = 0; c < 4; ++c) {
                if (f[c] > T0F) {
                    uint32_t pos = atomicAdd(&wcnt[wid], 1u);
                    if (pos < SEG) stage[wid * SEG + pos] = __float_as_uint(f[c]);
                }
            }
        }
    }
    __syncthreads();

    const uint32_t unitbase = (uint32_t)cta * 8;
    if (tid < 8) g_cnt[unitbase + tid] = wcnt[tid];
    for (int i = tid; i < 8 * SEG; i += 256) {
        int w = i / SEG, s = i - w * SEG;
        uint32_t c = wcnt[w];
        if ((uint32_t)s < (c < SEG ? c : (uint32_t)SEG))
            g_seg[(unitbase + w) * SEG + s] = stage[i];
    }
}

// ---------------------------------------------------------------------------
// K2: one WARP per row. Register-resident exact bitwise select, no block
// barriers, no histograms, no atomics on the hot path.
// ---------------------------------------------------------------------------
__global__ void __launch_bounds__(32 * K2_WARPS)
select_kernel(const float* __restrict__ x, float* __restrict__ out) {
    __shared__ uint32_t sel_all[K2_WARPS][KSEL];
    __shared__ uint32_t fcnt[K2_WARPS];

    const int widx = threadIdx.x >> 5;
    const int lane = threadIdx.x & 31;
    const int row  = blockIdx.x * K2_WARPS + widx;

    uint32_t* sel = sel_all[widx];

    // Per-unit counts: lanes 0..15 hold them.
    uint32_t myc = (lane < UNITS_PER_ROW) ? g_cnt[row * UNITS_PER_ROW + lane] : 0u;
    const uint32_t total = __reduce_add_sync(0xFFFFFFFFu, myc);
    const bool ovf = __any_sync(0xFFFFFFFFu, myc > SEG);
    const bool fb  = ovf || (total < KSEL);

    uint32_t T;          // transformed bit pattern of the 64th largest
    uint32_t total_gt;   // # strictly greater than T (<= 63)

    if (!fb) {
        // ---- Gather 24 candidates per lane (2 lanes per unit, 24 slots each) ----
        const int unit  = lane >> 1;
        const int sbase = (lane & 1) * 24;
        const uint32_t cu = __shfl_sync(0xFFFFFFFFu, myc, unit);
        const uint32_t* segp = g_seg + ((size_t)row * UNITS_PER_ROW + unit) * SEG + sbase;

        uint32_t t[24];
        #pragma unroll
        for (int j = 0; j < 24; ++j) {
            uint32_t raw = segp[j];  // static buffer: always safe to read
            t[j] = ((uint32_t)(sbase + j) < cu) ? (raw | 0x80000000u) : 0u;
        }

        // ---- Exact 32-step bitwise binary search for T (register-only) ----
        T = 0;
        #pragma unroll 1
        for (int b = 31; b >= 0; --b) {
            const uint32_t c = T | (1u << b);
            int loc = 0;
            #pragma unroll
            for (int j = 0; j < 24; ++j) loc += (int)(t[j] >= c);
            if (__reduce_add_sync(0xFFFFFFFFu, loc) >= KSEL) T = c;
        }

        // ---- Compact strict survivors via shfl exclusive scan ----
        int cg = 0;
        #pragma unroll
        for (int j = 0; j < 24; ++j) cg += (int)(t[j] > T);
        int off = cg;
        #pragma unroll
        for (int d = 1; d < 32; d <<= 1) {
            int v = __shfl_up_sync(0xFFFFFFFFu, off, d);
            if (lane >= d) off += v;
        }
        total_gt = (uint32_t)__shfl_sync(0xFFFFFFFFu, off, 31);
        off -= cg;  // exclusive
        #pragma unroll
        for (int j = 0; j < 24; ++j)
            if (t[j] > T) sel[off++] = t[j];
        __syncwarp();
    } else {
        // ---- Exact fallback over the full row (any input distribution) ----
        const uint32_t* src = reinterpret_cast<const uint32_t*>(x) + (size_t)row * ROW_LEN;
        T = 0;
        #pragma unroll 1
        for (int b = 31; b >= 0; --b) {
            const uint32_t c = T | (1u << b);
            int loc = 0;
            for (int i = lane; i < ROW_LEN; i += 32)
                loc += (int)(fwd_xform(src[i]) >= c);
            if (__reduce_add_sync(0xFFFFFFFFu, loc) >= KSEL) T = c;
        }
        if (lane == 0) fcnt[widx] = 0;
        __syncwarp();
        for (int i = lane; i < ROW_LEN; i += 32) {
            uint32_t u = fwd_xform(src[i]);
            if (u > T) sel[atomicAdd(&fcnt[widx], 1u)] = u;  // < 64 by construction
        }
        __syncwarp();
        total_gt = fcnt[widx];
    }

    // ---- Tie fill + rank-sort 64 winners (descending), write ----
    #pragma unroll
    for (int r = 0; r < 2; ++r) {
        int i = lane + 32 * r;
        if ((uint32_t)i >= total_gt) sel[i] = T;
    }
    __syncwarp();

    #pragma unroll
    for (int r = 0; r < 2; ++r) {
        const int i = lane + 32 * r;
        const uint32_t v = sel[i];
        int rank = 0;
        #pragma unroll
        for (int j = 0; j < KSEL; ++j) {
            uint32_t u = sel[j];
            rank += (int)((u > v) | ((u == v) & (j < i)));
        }
        out[(size_t)row * KSEL + rank] = inv_xform(v);
    }
}

extern "C" void kernel_launch(void* const* d_in, const int* in_sizes, int n_in,
                              void* d_out, int out_size) {
    const float* x = (const float*)d_in[0];
    float* out = (float*)d_out;
    int rows = in_sizes[0] / ROW_LEN;
    if (rows > MAXROWS) rows = MAXROWS;
    filter_kernel<<<rows * 2, 256>>>(x);
    select_kernel<<<rows / K2_WARPS, 32 * K2_WARPS>>>(x, out);
}

// round 10
// speedup vs baseline: 5.5332x; 1.1307x over previous
#include <cuda_runtime.h>
#include <cstdint>

#define ROW_LEN   16384
#define KSEL      64
#define MAXROWS   8192
#define UNITS_PER_ROW 16          // 2 CTAs/row x 8 warps in K1
#define SEG       48              // candidate slots per warp-unit
#define T0F       2.30f           // filter threshold; exact fallback covers any input
#define K2_WARPS  8
#define DCAP      256             // dense candidate capacity (8 regs/lane)
#define DREG      8

// Global scratch (static — no allocations).
__device__ uint32_t g_cnt[MAXROWS * UNITS_PER_ROW];
__device__ uint32_t g_seg[MAXROWS * UNITS_PER_ROW * SEG];   // ~25 MB (L2-resident)

// Monotonic transform: descending float order == descending uint order.
__device__ __forceinline__ uint32_t fwd_xform(uint32_t u) {
    return (u & 0x80000000u) ? ~u : (u | 0x80000000u);
}
__device__ __forceinline__ float inv_xform(uint32_t u) {
    return __uint_as_float((u & 0x80000000u) ? (u ^ 0x80000000u) : ~u);
}

// ---------------------------------------------------------------------------
// K1: pure streaming filter. One CTA per half-row. Proven ~80 us (~6.3 TB/s).
// ---------------------------------------------------------------------------
__global__ void __launch_bounds__(256, 6)
filter_kernel(const float* __restrict__ x) {
    __shared__ uint32_t wcnt[8];
    __shared__ uint32_t stage[8 * SEG];

    const int cta  = blockIdx.x;
    const int tid  = threadIdx.x;
    const int wid  = tid >> 5;

    if (tid < 8) wcnt[tid] = 0;
    __syncthreads();

    const float4* src4 = reinterpret_cast<const float4*>(x) + (size_t)cta * 2048;

    #pragma unroll
    for (int ot = 0; ot < 2; ++ot) {
        float4 v[4];
        #pragma unroll
        for (int j = 0; j < 4; ++j)
            v[j] = src4[(ot * 4 + j) * 256 + tid];
        #pragma unroll
        for (int j = 0; j < 4; ++j) {
            float f[4] = {v[j].x, v[j].y, v[j].z, v[j].w};
            #pragma unroll
            for (int c = 0; c < 4; ++c) {
                if (f[c] > T0F) {
                    uint32_t pos = atomicAdd(&wcnt[wid], 1u);
                    if (pos < SEG) stage[wid * SEG + pos] = __float_as_uint(f[c]);
                }
            }
        }
    }
    __syncthreads();

    const uint32_t unitbase = (uint32_t)cta * 8;
    if (tid < 8) g_cnt[unitbase + tid] = wcnt[tid];
    for (int i = tid; i < 8 * SEG; i += 256) {
        int w = i / SEG, s = i - w * SEG;
        uint32_t c = wcnt[w];
        if ((uint32_t)s < (c < SEG ? c : (uint32_t)SEG))
            g_seg[(unitbase + w) * SEG + s] = stage[i];
    }
}

// ---------------------------------------------------------------------------
// K2: one WARP per row. Dense-compacted candidates (8 regs/lane) + common-
// prefix-skipped exact bitwise select. No block barriers, no histograms.
// ---------------------------------------------------------------------------
__global__ void __launch_bounds__(32 * K2_WARPS)
select_kernel(const float* __restrict__ x, float* __restrict__ out) {
    __shared__ uint32_t dense_all[K2_WARPS][DCAP];
    __shared__ uint32_t sel_all[K2_WARPS][KSEL];
    __shared__ uint32_t fcnt[K2_WARPS];

    const int widx = threadIdx.x >> 5;
    const int lane = threadIdx.x & 31;
    const int row  = blockIdx.x * K2_WARPS + widx;

    uint32_t* dense = dense_all[widx];
    uint32_t* sel   = sel_all[widx];

    // Per-unit counts live in lanes 0..15.
    uint32_t myc = (lane < UNITS_PER_ROW) ? g_cnt[row * UNITS_PER_ROW + lane] : 0u;
    const uint32_t total = __reduce_add_sync(0xFFFFFFFFu, myc);
    const bool ovf = __any_sync(0xFFFFFFFFu, myc > SEG);
    const bool fb  = ovf || (total < KSEL) || (total > DCAP);

    uint32_t T;          // transformed bit pattern of the 64th largest
    uint32_t total_gt;   // # strictly greater than T (<= 63)

    if (!fb) {
        // ---- Exclusive prefix of unit counts (lanes >=16 contribute 0) ----
        uint32_t off = myc;
        #pragma unroll
        for (int d = 1; d < 32; d <<= 1) {
            uint32_t v = __shfl_up_sync(0xFFFFFFFFu, off, d);
            if (lane >= d) off += v;
        }
        const uint32_t excl_me = off - myc;

        // ---- Zero-pad dense strip, then compact (2 lanes per unit) ----
        #pragma unroll
        for (int r = 0; r < DCAP / 32; ++r) dense[lane + 32 * r] = 0;
        __syncwarp();

        const int unit = lane >> 1;
        const int sub  = lane & 1;
        const uint32_t cu   = __shfl_sync(0xFFFFFFFFu, myc, unit);
        const uint32_t base = __shfl_sync(0xFFFFFFFFu, excl_me, unit);
        const uint32_t* segp = g_seg + ((size_t)row * UNITS_PER_ROW + unit) * SEG;

        uint32_t land = 0xFFFFFFFFu, lor = 0;  // AND/OR over real candidates
        for (uint32_t j = sub; j < cu; j += 2) {
            uint32_t v = segp[j] | 0x80000000u;   // transformed (all positive)
            dense[base + j] = v;
            land &= v; lor |= v;
        }
        const uint32_t and_all = __reduce_and_sync(0xFFFFFFFFu, land);
        const uint32_t or_all  = __reduce_or_sync(0xFFFFFFFFu, lor);
        __syncwarp();

        // ---- Load 8 dense words into registers ----
        uint32_t t[DREG];
        #pragma unroll
        for (int r = 0; r < DREG; ++r) t[r] = dense[lane + 32 * r];

        // ---- Bitwise search, skipping the common prefix ----
        const uint32_t diff = and_all ^ or_all;
        if (diff == 0) {
            T = and_all;  // all candidates identical; total >= 64 guaranteed
        } else {
            const int hb = 31 - __clz(diff);
            T = (hb == 31) ? 0u : (and_all & ~((2u << hb) - 1u));
            #pragma unroll 1
            for (int b = hb; b >= 0; --b) {
                const uint32_t c = T | (1u << b);
                int loc = 0;
                #pragma unroll
                for (int r = 0; r < DREG; ++r) loc += (int)(t[r] >= c);
                if (__reduce_add_sync(0xFFFFFFFFu, loc) >= KSEL) T = c;
            }
        }

        // ---- Compact strict survivors via shfl exclusive scan ----
        int cg = 0;
        #pragma unroll
        for (int r = 0; r < DREG; ++r) cg += (int)(t[r] > T);
        int so = cg;
        #pragma unroll
        for (int d = 1; d < 32; d <<= 1) {
            int v = __shfl_up_sync(0xFFFFFFFFu, so, d);
            if (lane >= d) so += v;
        }
        total_gt = (uint32_t)__shfl_sync(0xFFFFFFFFu, so, 31);
        so -= cg;  // exclusive
        #pragma unroll
        for (int r = 0; r < DREG; ++r)
            if (t[r] > T) sel[so++] = t[r];
        __syncwarp();
    } else {
        // ---- Exact fallback over the full row (any input distribution) ----
        const uint32_t* src = reinterpret_cast<const uint32_t*>(x) + (size_t)row * ROW_LEN;
        T = 0;
        #pragma unroll 1
        for (int b = 31; b >= 0; --b) {
            const uint32_t c = T | (1u << b);
            int loc = 0;
            for (int i = lane; i < ROW_LEN; i += 32)
                loc += (int)(fwd_xform(src[i]) >= c);
            if (__reduce_add_sync(0xFFFFFFFFu, loc) >= KSEL) T = c;
        }
        if (lane == 0) fcnt[widx] = 0;
        __syncwarp();
        for (int i = lane; i < ROW_LEN; i += 32) {
            uint32_t u = fwd_xform(src[i]);
            if (u > T) sel[atomicAdd(&fcnt[widx], 1u)] = u;  // < 64 by construction
        }
        __syncwarp();
        total_gt = fcnt[widx];
    }

    // ---- Tie fill + rank-sort 64 winners (descending), write ----
    #pragma unroll
    for (int r = 0; r < 2; ++r) {
        int i = lane + 32 * r;
        if ((uint32_t)i >= total_gt) sel[i] = T;
    }
    __syncwarp();

    #pragma unroll
    for (int r = 0; r < 2; ++r) {
        const int i = lane + 32 * r;
        const uint32_t v = sel[i];
        int rank = 0;
        #pragma unroll
        for (int j = 0; j < KSEL; ++j) {
            uint32_t u = sel[j];
            rank += (int)((u > v) | ((u == v) & (j < i)));
        }
        out[(size_t)row * KSEL + rank] = inv_xform(v);
    }
}

extern "C" void kernel_launch(void* const* d_in, const int* in_sizes, int n_in,
                              void* d_out, int out_size) {
    const float* x = (const float*)d_in[0];
    float* out = (float*)d_out;
    int rows = in_sizes[0] / ROW_LEN;
    if (rows > MAXROWS) rows = MAXROWS;
    filter_kernel<<<rows * 2, 256>>>(x);
    select_kernel<<<rows / K2_WARPS, 32 * K2_WARPS>>>(x, out);
}